// round 8
// baseline (speedup 1.0000x reference)
#include <cuda_runtime.h>
#include <cuda_fp16.h>
#include <cstdint>
#include <cstddef>

#define N_TFH 1000
#define N_TG  20000
#define N_E   4000000
#define NV    (N_E / 4)          // 1,000,000 float4 groups
#define N_TAB (N_TG + N_TFH)     // 21,000 table entries
#define GRID    148
#define THREADS 256
#define TILE_V  256              // float4-groups per tile (1 per thread)
#define STAGES  3
#define NTILES  ((NV + TILE_V - 1) / TILE_V)   // 3907
#define STAGE_BYTES (9 * TILE_V * 16)          // 36,864
#define ARR_BYTES   (TILE_V * 16)              // 4,096 per array per stage
#define SMEM_TAB_OFF (STAGES * STAGE_BYTES)            // 110,592
#define SMEM_MBAR_OFF (SMEM_TAB_OFF + N_TAB * 4)       // 194,592
#define SMEM_TOTAL   (SMEM_MBAR_OFF + STAGES * 8)      // 194,616

__device__ __forceinline__ float warp_reduce(float v) {
    #pragma unroll
    for (int o = 16; o > 0; o >>= 1)
        v += __shfl_xor_sync(0xFFFFFFFFu, v, o);
    return v;
}

__device__ __forceinline__ uint32_t smem_u32(const void* p) {
    uint32_t a;
    asm("{ .reg .u64 t; cvta.to.shared.u64 t, %1; cvt.u32.u64 %0, t; }"
        : "=r"(a) : "l"(p));
    return a;
}
__device__ __forceinline__ void mbar_init(uint32_t mbar, uint32_t cnt) {
    asm volatile("mbarrier.init.shared.b64 [%0], %1;" :: "r"(mbar), "r"(cnt) : "memory");
}
__device__ __forceinline__ void mbar_expect_tx(uint32_t mbar, uint32_t bytes) {
    asm volatile("mbarrier.arrive.expect_tx.shared.b64 _, [%0], %1;"
                 :: "r"(mbar), "r"(bytes) : "memory");
}
__device__ __forceinline__ void mbar_wait(uint32_t mbar, uint32_t parity) {
    asm volatile(
        "{\n\t.reg .pred P;\n\t"
        "WL%=:\n\t"
        "mbarrier.try_wait.parity.acquire.cta.shared::cta.b64 P, [%0], %1, 0x989680;\n\t"
        "@P bra WD%=;\n\t"
        "bra WL%=;\n\t"
        "WD%=:\n\t}"
        :: "r"(mbar), "r"(parity) : "memory");
}
__device__ __forceinline__ void fence_async_shared() {
    asm volatile("fence.proxy.async.shared::cta;" ::: "memory");
}
__device__ __forceinline__ void tma_1d(uint32_t dst, const void* src,
                                       uint32_t bytes, uint32_t mbar) {
    asm volatile(
        "cp.async.bulk.shared::cta.global.mbarrier::complete_tx::bytes [%0], [%1], %2, [%3];"
        :: "r"(dst), "l"(src), "r"(bytes), "r"(mbar) : "memory");
}

__global__ void zero_out_kernel(float* out) { out[0] = 0.0f; }

__global__ __launch_bounds__(THREADS, 1)
void fused_loss_kernel(
    const float* __restrict__ TF_high_mu,
    const float* __restrict__ TF_high_sigma,
    const float* __restrict__ TG_mu,
    const float* __restrict__ TG_sigma,
    const float* __restrict__ TF_high_exp,
    const float* __restrict__ TG_exp,
    const char* __restrict__ k_edge,
    const char* __restrict__ alpha,
    const char* __restrict__ cov,
    const char* __restrict__ edge_y,
    const char* __restrict__ edge_x,
    const int*  __restrict__ father_num,
    const char* __restrict__ idx_tf_tg,
    const char* __restrict__ idx_tf_high,
    const char* __restrict__ edge_tg_idx,
    const char* __restrict__ is_high,
    float* __restrict__ out)
{
    extern __shared__ char smem[];
    __half2* s_tab = (__half2*)(smem + SMEM_TAB_OFF);
    const uint32_t smem_base = smem_u32(smem);
    const uint32_t mbar0 = smem_base + SMEM_MBAR_OFF;
    const int tid = threadIdx.x;
    const float HALF_LOG2PI = 0.918938533204672742f;

    // ---- build fp16 (mu,sigma) table in smem (coalesced global reads) ----
    for (int i = tid; i < N_TG; i += THREADS)
        s_tab[i] = __floats2half2_rn(TG_mu[i], TG_sigma[i]);
    for (int i = tid; i < N_TFH; i += THREADS)
        s_tab[N_TG + i] = __floats2half2_rn(TF_high_mu[i], TF_high_sigma[i]);

    if (tid == 0) {
        #pragma unroll
        for (int s = 0; s < STAGES; s++) mbar_init(mbar0 + s * 8, 1);
        fence_async_shared();
    }
    __syncthreads();

    // ---- pipeline prologue: issue first STAGES tiles ----
    if (tid == 0) {
        #pragma unroll
        for (int s = 0; s < STAGES; s++) {
            int t = blockIdx.x + s * GRID;
            if (t < NTILES) {
                uint32_t cnt   = (uint32_t)min(TILE_V, NV - t * TILE_V);
                uint32_t bytes = cnt * 16;
                uint32_t mb    = mbar0 + s * 8;
                size_t   off   = (size_t)t * ARR_BYTES;
                uint32_t dst   = smem_base + s * STAGE_BYTES;
                mbar_expect_tx(mb, 9 * bytes);
                tma_1d(dst + 0 * ARR_BYTES, k_edge      + off, bytes, mb);
                tma_1d(dst + 1 * ARR_BYTES, alpha       + off, bytes, mb);
                tma_1d(dst + 2 * ARR_BYTES, cov         + off, bytes, mb);
                tma_1d(dst + 3 * ARR_BYTES, edge_y      + off, bytes, mb);
                tma_1d(dst + 4 * ARR_BYTES, edge_x      + off, bytes, mb);
                tma_1d(dst + 5 * ARR_BYTES, idx_tf_tg   + off, bytes, mb);
                tma_1d(dst + 6 * ARR_BYTES, idx_tf_high + off, bytes, mb);
                tma_1d(dst + 7 * ARR_BYTES, edge_tg_idx + off, bytes, mb);
                tma_1d(dst + 8 * ARR_BYTES, is_high     + off, bytes, mb);
            }
        }
    }

    float acc = 0.0f;

    // ---- p/q terms (tiny; exact fp32 from global) ----
    const int gtid = blockIdx.x * THREADS + tid;
    if (gtid < N_TG) {
        float mu = TG_mu[gtid], sg = TG_sigma[gtid], x = TG_exp[gtid];
        float fn = (float)father_num[gtid];
        float z = (x - mu) / sg;
        float lp = -0.5f * z * z - __logf(sg) - HALF_LOG2PI;
        acc += (fn - 1.0f) * lp;                       // -q
    }
    if (gtid < N_TFH) {
        float mu = TF_high_mu[gtid], sg = TF_high_sigma[gtid], x = TF_high_exp[gtid];
        float z = (x - mu) / sg;
        acc += 0.5f * z * z + __logf(sg) + HALF_LOG2PI; // -p
    }

    // ---- main pipelined loop over tiles ----
    int k = 0;
    for (int t = blockIdx.x; t < NTILES; t += GRID, k++) {
        const int stage = k % STAGES;
        const uint32_t parity = (uint32_t)((k / STAGES) & 1);
        mbar_wait(mbar0 + stage * 8, parity);

        const int cnt = min(TILE_V, NV - t * TILE_V);
        if (tid < cnt) {
            const float4* st = (const float4*)(smem + stage * STAGE_BYTES);
            float4 ke = st[0 * TILE_V + tid];
            float4 al = st[1 * TILE_V + tid];
            float4 cv = st[2 * TILE_V + tid];
            float4 ey = st[3 * TILE_V + tid];
            float4 ex = st[4 * TILE_V + tid];
            int4  itg = ((const int4*)st)[5 * TILE_V + tid];
            int4  ith = ((const int4*)st)[6 * TILE_V + tid];
            int4  ieg = ((const int4*)st)[7 * TILE_V + tid];
            int4  ih  = ((const int4*)st)[8 * TILE_V + tid];

            const float* kef = &ke.x; const float* alf = &al.x;
            const float* cvf = &cv.x; const float* eyf = &ey.x;
            const float* exf = &ex.x;
            const int* itgf = &itg.x; const int* ithf = &ith.x;
            const int* iegf = &ieg.x; const int* ihf  = &ih.x;

            #pragma unroll
            for (int l = 0; l < 4; l++) {
                int tfi = ihf[l] ? (N_TG + ithf[l]) : itgf[l];
                float2 tf = __half22float2(s_tab[tfi]);
                float2 tg = __half22float2(s_tab[iegf[l]]);

                float inv_var = __frcp_rn(tf.y * tf.y);
                float loc = tg.x + kef[l] * cvf[l] * (eyf[l] - tf.x) * inv_var;
                loc = fmaxf(loc, 0.0f) + 0.01f;
                float var = tg.y * tg.y - alf[l] * alf[l] * inv_var;
                var = fmaxf(var, 0.0f) + 0.01f;

                float dx = exf[l] - loc;
                acc += 0.5f * (dx * dx * __frcp_rn(var) + __logf(var)) + HALF_LOG2PI;
            }
        }
        __syncthreads();   // whole block done reading this stage

        const int tn = t + GRID * STAGES;
        if (tid == 0 && tn < NTILES) {
            fence_async_shared();
            uint32_t cnt2   = (uint32_t)min(TILE_V, NV - tn * TILE_V);
            uint32_t bytes  = cnt2 * 16;
            uint32_t mb     = mbar0 + stage * 8;
            size_t   off    = (size_t)tn * ARR_BYTES;
            uint32_t dst    = smem_base + stage * STAGE_BYTES;
            mbar_expect_tx(mb, 9 * bytes);
            tma_1d(dst + 0 * ARR_BYTES, k_edge      + off, bytes, mb);
            tma_1d(dst + 1 * ARR_BYTES, alpha       + off, bytes, mb);
            tma_1d(dst + 2 * ARR_BYTES, cov         + off, bytes, mb);
            tma_1d(dst + 3 * ARR_BYTES, edge_y      + off, bytes, mb);
            tma_1d(dst + 4 * ARR_BYTES, edge_x      + off, bytes, mb);
            tma_1d(dst + 5 * ARR_BYTES, idx_tf_tg   + off, bytes, mb);
            tma_1d(dst + 6 * ARR_BYTES, idx_tf_high + off, bytes, mb);
            tma_1d(dst + 7 * ARR_BYTES, edge_tg_idx + off, bytes, mb);
            tma_1d(dst + 8 * ARR_BYTES, is_high     + off, bytes, mb);
        }
    }

    // ---- reduction ----
    acc = warp_reduce(acc);
    __shared__ float warp_sums[THREADS / 32];
    int lane = tid & 31, wid = tid >> 5;
    if (lane == 0) warp_sums[wid] = acc;
    __syncthreads();
    if (wid == 0) {
        float v = (lane < THREADS / 32) ? warp_sums[lane] : 0.0f;
        v = warp_reduce(v);
        if (lane == 0) atomicAdd(out, v);
    }
}

extern "C" void kernel_launch(void* const* d_in, const int* in_sizes, int n_in,
                              void* d_out, int out_size) {
    cudaFuncSetAttribute(fused_loss_kernel,
                         cudaFuncAttributeMaxDynamicSharedMemorySize, SMEM_TOTAL);

    float* out = (float*)d_out;
    zero_out_kernel<<<1, 1>>>(out);

    fused_loss_kernel<<<GRID, THREADS, SMEM_TOTAL>>>(
        (const float*)d_in[0], (const float*)d_in[1],
        (const float*)d_in[2], (const float*)d_in[3],
        (const float*)d_in[4], (const float*)d_in[5],
        (const char*)d_in[6],  (const char*)d_in[7],
        (const char*)d_in[8],  (const char*)d_in[9],
        (const char*)d_in[10], (const int*)d_in[11],
        (const char*)d_in[12], (const char*)d_in[13],
        (const char*)d_in[14], (const char*)d_in[15],
        out);
}

// round 9
// speedup vs baseline: 1.4234x; 1.4234x over previous
#include <cuda_runtime.h>
#include <cstdint>
#include <cstddef>

#define N_TFH 1000
#define N_TG  20000
#define N_E   4000000
#define NV    (N_E / 4)          // 1,000,000 float4 groups
#define N_TAB (N_TG + N_TFH)     // 21,000 table entries
#define GRID    148
#define THREADS 768
#define SMEM_BYTES (N_TAB * 8)   // float2 table: 168,000 B

__device__ __forceinline__ float warp_reduce(float v) {
    #pragma unroll
    for (int o = 16; o > 0; o >>= 1)
        v += __shfl_xor_sync(0xFFFFFFFFu, v, o);
    return v;
}

// FFMA-pipe reciprocal: bit-magic seed + 3 Newton iterations (~1e-10 rel err).
// No MUFU. Valid for positive normal x (here x in [0.01, ~70]).
__device__ __forceinline__ float fast_rcp(float x) {
    float r = __int_as_float(0x7EF311C3 - __float_as_int(x));
    r = r * fmaf(-x, r, 2.0f);
    r = r * fmaf(-x, r, 2.0f);
    r = r * fmaf(-x, r, 2.0f);
    return r;
}

// FFMA-pipe natural log (njuffa-style), ~1e-7 rel. No MUFU.
__device__ __forceinline__ float fast_logf(float a) {
    int e = (__float_as_int(a) - 0x3f2aaaab) & 0xff800000;
    float m = __int_as_float(__float_as_int(a) - e);   // m in [2/3, 4/3)
    float i = (float)e * 1.19209290e-7f;               // e * 2^-23
    float f = m - 1.0f;
    float s = f * f;
    // log1p(f) for f in [-1/3, 1/3]
    float r = fmaf(0.230836749f, f, -0.279208571f);
    float t = fmaf(0.331826031f, f, -0.498910338f);
    r = fmaf(r, s, t);
    r = fmaf(r, s, f);
    r = fmaf(i, 0.693147182f, r);
    return r;
}

__global__ void zero_out_kernel(float* out) { out[0] = 0.0f; }

__global__ __launch_bounds__(THREADS, 1)
void fused_loss_kernel(
    const float* __restrict__ TF_high_mu,
    const float* __restrict__ TF_high_sigma,
    const float* __restrict__ TG_mu,
    const float* __restrict__ TG_sigma,
    const float* __restrict__ TF_high_exp,
    const float* __restrict__ TG_exp,
    const float4* __restrict__ k_edge,
    const float4* __restrict__ alpha,
    const float4* __restrict__ cov,
    const float4* __restrict__ edge_y,
    const float4* __restrict__ edge_x,
    const int*   __restrict__ father_num,
    const int4*  __restrict__ idx_tf_tg,
    const int4*  __restrict__ idx_tf_high,
    const int4*  __restrict__ edge_tg_idx,
    const int4*  __restrict__ is_high,
    float* __restrict__ out)
{
    extern __shared__ float2 s_tab[];   // (mu, sigma^2), fp32, 168 KB
    const float HALF_LOG2PI = 0.918938533204672742f;
    const int tid = threadIdx.x;

    // ---- build (mu, sig^2) table from coalesced reads ----
    for (int i = tid; i < N_TG; i += THREADS) {
        float sg = TG_sigma[i];
        s_tab[i] = make_float2(TG_mu[i], sg * sg);
    }
    for (int i = tid; i < N_TFH; i += THREADS) {
        float sg = TF_high_sigma[i];
        s_tab[N_TG + i] = make_float2(TF_high_mu[i], sg * sg);
    }
    __syncthreads();

    float acc = 0.0f;
    const int gtid   = blockIdx.x * THREADS + tid;
    const int stride = GRID * THREADS;

    // ---- p/q terms (21k elems total; MUFU here is negligible) ----
    if (gtid < N_TG) {
        float mu = TG_mu[gtid], sg = TG_sigma[gtid], x = TG_exp[gtid];
        float fn = (float)father_num[gtid];
        float z = (x - mu) / sg;
        float lp = -0.5f * z * z - fast_logf(sg) - HALF_LOG2PI;
        acc += (fn - 1.0f) * lp;                         // -q
    }
    if (gtid < N_TFH) {
        float mu = TF_high_mu[gtid], sg = TF_high_sigma[gtid], x = TF_high_exp[gtid];
        float z = (x - mu) / sg;
        acc += 0.5f * z * z + fast_logf(sg) + HALF_LOG2PI; // -p
    }

    // ---- edge term: MUFU-free inner loop ----
    for (int v = gtid; v < NV; v += stride) {
        float4 ke = k_edge[v];
        float4 al = alpha[v];
        float4 cv = cov[v];
        float4 ey = edge_y[v];
        float4 ex = edge_x[v];
        int4  itg = idx_tf_tg[v];
        int4  ith = idx_tf_high[v];
        int4  ieg = edge_tg_idx[v];
        int4  ih  = is_high[v];

        const float* kef = &ke.x; const float* alf = &al.x;
        const float* cvf = &cv.x; const float* eyf = &ey.x;
        const float* exf = &ex.x;
        const int* itgf = &itg.x; const int* ithf = &ith.x;
        const int* iegf = &ieg.x; const int* ihf  = &ih.x;

        #pragma unroll
        for (int l = 0; l < 4; l++) {
            int tfi = ihf[l] ? (N_TG + ithf[l]) : itgf[l];
            float2 tf = s_tab[tfi];          // (tf_mu, tf_sig^2)
            float2 tg = s_tab[iegf[l]];      // (tg_mu, tg_sig^2)

            float iv  = fast_rcp(tf.y);                       // 1/tf_sig^2
            float loc = fmaf(kef[l] * cvf[l], (eyf[l] - tf.x) * iv, tg.x);
            loc = fmaxf(loc, 0.0f) + 0.01f;
            float var = fmaf(-alf[l] * alf[l], iv, tg.y);
            var = fmaxf(var, 0.0f) + 0.01f;

            float dx = exf[l] - loc;
            // -logprob = 0.5*(dx^2/var + log(var)) + 0.5*log(2pi)
            acc += fmaf(0.5f, fmaf(dx * dx, fast_rcp(var), fast_logf(var)),
                        HALF_LOG2PI);
        }
    }

    // ---- block reduction -> one atomic per block ----
    acc = warp_reduce(acc);
    __shared__ float warp_sums[THREADS / 32];
    int lane = tid & 31, wid = tid >> 5;
    if (lane == 0) warp_sums[wid] = acc;
    __syncthreads();
    if (wid == 0) {
        float v = (lane < THREADS / 32) ? warp_sums[lane] : 0.0f;
        v = warp_reduce(v);
        if (lane == 0) atomicAdd(out, v);
    }
}

extern "C" void kernel_launch(void* const* d_in, const int* in_sizes, int n_in,
                              void* d_out, int out_size) {
    cudaFuncSetAttribute(fused_loss_kernel,
                         cudaFuncAttributeMaxDynamicSharedMemorySize, SMEM_BYTES);

    float* out = (float*)d_out;
    zero_out_kernel<<<1, 1>>>(out);

    fused_loss_kernel<<<GRID, THREADS, SMEM_BYTES>>>(
        (const float*)d_in[0], (const float*)d_in[1],
        (const float*)d_in[2], (const float*)d_in[3],
        (const float*)d_in[4], (const float*)d_in[5],
        (const float4*)d_in[6], (const float4*)d_in[7],
        (const float4*)d_in[8], (const float4*)d_in[9],
        (const float4*)d_in[10], (const int*)d_in[11],
        (const int4*)d_in[12], (const int4*)d_in[13],
        (const int4*)d_in[14], (const int4*)d_in[15],
        out);
}